// round 13
// baseline (speedup 1.0000x reference)
#include <cuda_runtime.h>
#include <math.h>
#include <stdint.h>

typedef unsigned long long u64;

// ---------------- device-global scratch (no allocs allowed) ----------------
__device__ __align__(16) float  g_w0q[320];      // 5x64 quantized fp32
__device__ __align__(16) float  g_wk[3][4096];   // w1..w3 integer codes 0..63 ([k][j])
__device__ __align__(8)  float  g_qp[3][2];      // {scale, mn} per layer
__device__ __align__(16) float  g_w4q[64];
__device__ __align__(16) float  g_b0q[64];
__device__ __align__(16) float  g_bq[3][64];
__device__ __align__(16) float  g_b4q[4];
__device__ float4 g_grid0[128];
__device__ float4 g_grid1[512];
__device__ float4 g_grid2[2048];

// ---------------- packed helpers (layer-0 only) -----------------------------
__device__ __forceinline__ u64 pack2(float lo, float hi) {
    u64 r;
    asm("mov.b64 %0, {%1, %2};" : "=l"(r) : "f"(lo), "f"(hi));
    return r;
}
__device__ __forceinline__ void unpack2(u64 v, float& lo, float& hi) {
    asm("mov.b64 {%0, %1}, %2;" : "=f"(lo), "=f"(hi) : "l"(v));
}
__device__ __forceinline__ u64 fma2(u64 a, u64 b, u64 c) {
    u64 d;
    asm("fma.rn.f32x2 %0, %1, %2, %3;" : "=l"(d) : "l"(a), "l"(b), "l"(c));
    return d;
}
__device__ __forceinline__ u64 dup2(float c) { return pack2(c, c); }
__device__ __forceinline__ float rcp_fast(float x) {
    float r; asm("rcp.approx.f32 %0, %1;" : "=f"(r) : "f"(x)); return r;
}
__device__ __forceinline__ float ex2_fast(float x) {
    float r; asm("ex2.approx.f32 %0, %1;" : "=f"(r) : "f"(x)); return r;
}
__device__ __forceinline__ uint32_t tf32_rna(float x) {
    uint32_t r;
    asm("cvt.rna.tf32.f32 %0, %1;" : "=r"(r) : "f"(x));
    return r;
}

// ---------------- scalar GELU, A&S 7.1.25 (3-term, |erf err| <= 2.5e-5) -----
// gelu(x) = 0.5x + |0.5x| * erf(|x|/sqrt2); fabsf folds into SASS modifiers.
__device__ __forceinline__ float gelu3(float x) {
    float w  = fmaf(fabsf(x), 0.33267982f, 1.0f);   // 1 + 0.47047*|x|/sqrt2
    float t  = rcp_fast(w);
    float q  = fmaf(0.7478556f, t, -0.0958798f);
    q = fmaf(q, t, 0.3480242f);
    float s  = q * t;
    float e  = ex2_fast(x * x * -0.7213475204f);    // exp(-x^2/2) via ex2
    float ea = fmaf(-s, e, 1.0f);                   // erf(|x|/sqrt2)
    float hx = 0.5f * x;
    return fmaf(fabsf(hx), ea, hx);
}

// tf32 tensor-core mma (base PTX, sm_80+): D += A x B  (m16n8k8)
__device__ __forceinline__ void mma_tf32(float d[4], const uint32_t a[4],
                                         uint32_t b0, uint32_t b1) {
    asm volatile(
        "mma.sync.aligned.m16n8k8.row.col.f32.tf32.tf32.f32 "
        "{%0,%1,%2,%3}, {%4,%5,%6,%7}, {%8,%9}, {%0,%1,%2,%3};"
        : "+f"(d[0]), "+f"(d[1]), "+f"(d[2]), "+f"(d[3])
        : "r"(a[0]), "r"(a[1]), "r"(a[2]), "r"(a[3]), "r"(b0), "r"(b1));
}

// ---------------- merged prep: quantization + grid tables -------------------
__global__ void prep_kernel(const float* w0, const float* w1, const float* w2,
                            const float* w3, const float* w4,
                            const float* b0, const float* b1, const float* b2,
                            const float* b3, const float* b4,
                            const float* ind0, const float* cb0,
                            const float* ind1, const float* cb1,
                            const float* ind2, const float* cb2)
{
    int t = threadIdx.x;
    if (blockIdx.x >= 10) {
        int idx = (blockIdx.x - 10) * 256 + t;
        const float* ind; const float* cb; float4* dst; int row;
        if (idx < 128)       { ind = ind0; cb = cb0; dst = g_grid0; row = idx; }
        else if (idx < 640)  { ind = ind1; cb = cb1; dst = g_grid1; row = idx - 128; }
        else if (idx < 2688) { ind = ind2; cb = cb2; dst = g_grid2; row = idx - 640; }
        else return;
        const float* r = ind + (long)row * 64;
        float best = r[0]; int arg = 0;
        #pragma unroll
        for (int j = 1; j < 64; j++) {
            float v = r[j];
            if (v > best) { best = v; arg = j; }   // strict > == first-occurrence
        }
        dst[row] = make_float4(cb[arg * 4 + 0], cb[arg * 4 + 1],
                               cb[arg * 4 + 2], cb[arg * 4 + 3]);
        return;
    }

    __shared__ float smin[256], smax[256];
    const float* src; float* dst; int n; int kcode = 0;
    switch (blockIdx.x) {
        case 0: src = w0; dst = g_w0q;   n = 320;  break;
        case 1: src = w1; dst = g_wk[0]; n = 4096; kcode = 1; break;
        case 2: src = w2; dst = g_wk[1]; n = 4096; kcode = 1; break;
        case 3: src = w3; dst = g_wk[2]; n = 4096; kcode = 1; break;
        case 4: src = w4; dst = g_w4q;   n = 64;   break;
        case 5: src = b0; dst = g_b0q;   n = 64;   break;
        case 6: src = b1; dst = g_bq[0]; n = 64;   break;
        case 7: src = b2; dst = g_bq[1]; n = 64;   break;
        case 8: src = b3; dst = g_bq[2]; n = 64;   break;
        default: src = b4; dst = g_b4q;  n = 1;    break;
    }
    float mn = INFINITY, mx = -INFINITY;
    for (int i = t; i < n; i += 256) {
        float v = src[i];
        mn = fminf(mn, v); mx = fmaxf(mx, v);
    }
    smin[t] = mn; smax[t] = mx;
    __syncthreads();
    for (int s = 128; s > 0; s >>= 1) {
        if (t < s) {
            smin[t] = fminf(smin[t], smin[t + s]);
            smax[t] = fmaxf(smax[t], smax[t + s]);
        }
        __syncthreads();
    }
    mn = smin[0]; mx = smax[0];
    float scale = fmaxf(mx - mn, 1e-8f) / 63.0f;
    if (kcode) {
        for (int i = t; i < n; i += 256)
            dst[i] = rintf((src[i] - mn) / scale);   // integer code 0..63
        if (t == 0) {
            g_qp[blockIdx.x - 1][0] = scale;
            g_qp[blockIdx.x - 1][1] = mn;
        }
    } else {
        for (int i = t; i < n; i += 256)
            dst[i] = rintf((src[i] - mn) / scale) * scale + mn;
    }
}

// ---------------- main tensor-core kernel -----------------------------------
// Single-product tf32 MMA: W_q = scale*K + mn*J, K integer (exact tf32).
// x@W_q = scale*(tf32(x)@K) + mn*S, with S computed BY THE MMA via a virtual
// all-ones B tile (d8 = A @ 1). Epilogue is fully SCALAR (no f32x2 pack/unpack
// MOV traffic): 3-term erf gelu, fabs via free SASS source modifiers.
// D->A is a pure register renaming (A=[d0,d2,d1,d3]) via the B row
// permutation sigma(p)=2p|2(p-4)+1.
//
// smem (bytes):
//   0     : wf — B codes [3l][8kt][8nt][32 lanes] x uint2 = 49152
//   49152 : w0s[320f], 50432: b0s[64f], 50688: bz[3][64f], 51456: w4s[64f],
//   51712 : b4f[4f], 51728: qp[8f], 51760: in5s[5][128f]
#define OFF_WF    0
#define OFF_W0S   49152
#define OFF_B0S   50432
#define OFF_BZ    50688
#define OFF_W4S   51456
#define OFF_B4F   51712
#define OFF_QP    51728
#define OFF_IN5   51760
#define SMEM_BYTES 54320

__global__ void __launch_bounds__(128, 4)
mlp_tc_kernel(const float* __restrict__ x, float* __restrict__ out, int ntiles)
{
    extern __shared__ char smp[];
    const uint2* wf = (const uint2*)(smp + OFF_WF);
    float* w0s = (float*)(smp + OFF_W0S);
    float* b0s = (float*)(smp + OFF_B0S);
    float* bz  = (float*)(smp + OFF_BZ);
    float* w4s = (float*)(smp + OFF_W4S);
    float* b4f = (float*)(smp + OFF_B4F);
    float* qps = (float*)(smp + OFF_QP);
    float* in5s = (float*)(smp + OFF_IN5);

    int t = threadIdx.x;
    int wid = t >> 5;
    int lane = t & 31;
    int g = lane >> 2;      // row group 0..7
    int tig = lane & 3;     // thread-in-group

    const uint32_t ONEB = 0x3f800000u;   // 1.0f bits (exact tf32)

    // ---- one-time staging ----
    {
        uint2* wfw = (uint2*)(smp + OFF_WF);
        for (int e = t; e < 6144; e += 128) {
            int el = e & 31, nt = (e >> 5) & 7, kt = (e >> 8) & 7, l = e >> 11;
            int eg = el >> 2, etig = el & 3;
            int j = 8 * nt + eg;
            int k0 = 8 * kt + 2 * etig;
            const float* wl = g_wk[l];
            wfw[e] = make_uint2(__float_as_uint(wl[k0 * 64 + j]),
                                __float_as_uint(wl[(k0 + 1) * 64 + j]));
        }
    }
    for (int i = t; i < 320; i += 128) w0s[i] = g_w0q[i];
    if (t < 64) {
        b0s[t] = g_b0q[t];
        bz[t] = g_bq[0][t]; bz[64 + t] = g_bq[1][t]; bz[128 + t] = g_bq[2][t];
        w4s[t] = g_w4q[t];
        if (t == 0) b4f[0] = g_b4q[0];
        if (t < 6) qps[t] = ((const float*)g_qp)[t];
    }

    for (int tile = blockIdx.x; tile < ntiles; tile += gridDim.x) {
        __syncthreads();

        // ---- interp: one point per thread -> in5s[5][128] ----
        int gidx = tile * 128 + t;
        {
            float2 xv = __ldg((const float2*)x + gidx);
            float feat = xv.x;
            float tc = (xv.y + 1.0f) * 0.5f;
            float4 gg = make_float4(0.f, 0.f, 0.f, 0.f);
            auto interp_add = [&](const float4* __restrict__ tab, int res) {
                float c = tc * (float)(res - 1);
                int left  = min((int)floorf(c), res - 2);
                int right = max((int)ceilf(c), 1);
                float w = c - (float)left;
                float4 gl = __ldg(tab + left);
                float4 gr = __ldg(tab + right);
                gg.x += (1.0f - w) * gl.x + w * gr.x;
                gg.y += (1.0f - w) * gl.y + w * gr.y;
                gg.z += (1.0f - w) * gl.z + w * gr.z;
                gg.w += (1.0f - w) * gl.w + w * gr.w;
            };
            interp_add(g_grid0, 128);
            interp_add(g_grid1, 512);
            interp_add(g_grid2, 2048);
            in5s[0 * 128 + t] = gg.x;
            in5s[1 * 128 + t] = gg.y;
            in5s[2 * 128 + t] = gg.z;
            in5s[3 * 128 + t] = gg.w;
            in5s[4 * 128 + t] = feat;
        }
        __syncthreads();

        // ---- each warp: 2 sequential m16 sub-tiles ----
        #pragma unroll 1
        for (int s = 0; s < 2; s++) {
            int mt = wid + 4 * s;
            int poff = mt * 16;

            float d[8][4];
            float d8[4];                 // S fragment: A @ ones
            uint32_t A[8][4];            // tf32 A fragments (one per kt)

            // ---- layer 0 (5 -> 64) into D layout (packed fp32 fma) ----
            {
                float ia[5], ib[5];
                #pragma unroll
                for (int k = 0; k < 5; k++) {
                    ia[k] = in5s[k * 128 + poff + g];
                    ib[k] = in5s[k * 128 + poff + g + 8];
                }
                #pragma unroll
                for (int nt = 0; nt < 8; nt++) {
                    int f0 = 8 * nt + 2 * tig;
                    u64 a0 = pack2(0.f, 0.f), a1 = pack2(0.f, 0.f);
                    #pragma unroll
                    for (int k = 0; k < 5; k++) {
                        u64 wp = *(const u64*)(w0s + k * 64 + f0);
                        a0 = fma2(dup2(ia[k]), wp, a0);
                        a1 = fma2(dup2(ib[k]), wp, a1);
                    }
                    unpack2(a0, d[nt][0], d[nt][1]);
                    unpack2(a1, d[nt][2], d[nt][3]);
                }
            }

            // ---- scalar epilogue: scale*d + bias + off -> gelu -> tf32 A ----
            auto epi = [&](const float* bias, float scl, float offa, float offb) {
                #pragma unroll
                for (int nt = 0; nt < 8; nt++) {
                    int f0 = 8 * nt + 2 * tig;
                    float2 bb = *(const float2*)(bias + f0);
                    float a0 = fmaf(scl, d[nt][0], bb.x) + offa;
                    float a1 = fmaf(scl, d[nt][1], bb.y) + offa;
                    float a2 = fmaf(scl, d[nt][2], bb.x) + offb;
                    float a3 = fmaf(scl, d[nt][3], bb.y) + offb;
                    // D->A renaming: A = [gelu(d0), gelu(d2), gelu(d1), gelu(d3)]
                    A[nt][0] = tf32_rna(gelu3(a0));
                    A[nt][1] = tf32_rna(gelu3(a2));
                    A[nt][2] = tf32_rna(gelu3(a1));
                    A[nt][3] = tf32_rna(gelu3(a3));
                }
            };
            epi(b0s, 1.0f, 0.f, 0.f);

            // ---- 3 mma layers (single tf32 product + ones-column for S) ----
            float scl3 = 0.f, offa3 = 0.f, offb3 = 0.f;
            #pragma unroll 1
            for (int l = 0; l < 3; l++) {
                #pragma unroll
                for (int nt = 0; nt < 8; nt++) {
                    d[nt][0] = 0.f; d[nt][1] = 0.f;
                    d[nt][2] = 0.f; d[nt][3] = 0.f;
                }
                d8[0] = 0.f; d8[1] = 0.f; d8[2] = 0.f; d8[3] = 0.f;
                const uint2* wfl = wf + (size_t)l * 8 * 8 * 32;
                #pragma unroll
                for (int kt = 0; kt < 8; kt++) {
                    #pragma unroll
                    for (int nt = 0; nt < 8; nt++) {
                        uint2 B = wfl[(kt * 8 + nt) * 32 + lane];
                        mma_tf32(d[nt], A[kt], B.x, B.y);
                    }
                    mma_tf32(d8, A[kt], ONEB, ONEB);   // S accumulation
                }
                float scl = qps[2 * l], mn = qps[2 * l + 1];
                if (l < 2) epi(bz + 64 * l, scl, mn * d8[0], mn * d8[2]);
                else { scl3 = scl; offa3 = mn * d8[0]; offb3 = mn * d8[2]; }
            }

            // ---- final: scalar bias b3 + gelu + dot w4, reduce, tanh ----
            {
                const float* b3 = bz + 128;
                float sg = 0.f, sg8 = 0.f;
                #pragma unroll
                for (int nt = 0; nt < 8; nt++) {
                    int f0 = 8 * nt + 2 * tig;
                    float2 bb  = *(const float2*)(b3 + f0);
                    float2 w4v = *(const float2*)(w4s + f0);
                    float a0 = fmaf(scl3, d[nt][0], bb.x) + offa3;
                    float a1 = fmaf(scl3, d[nt][1], bb.y) + offa3;
                    float a2 = fmaf(scl3, d[nt][2], bb.x) + offb3;
                    float a3 = fmaf(scl3, d[nt][3], bb.y) + offb3;
                    sg  = fmaf(gelu3(a0), w4v.x, sg);
                    sg  = fmaf(gelu3(a1), w4v.y, sg);
                    sg8 = fmaf(gelu3(a2), w4v.x, sg8);
                    sg8 = fmaf(gelu3(a3), w4v.y, sg8);
                }
                sg  += __shfl_xor_sync(0xffffffffu, sg, 1);
                sg  += __shfl_xor_sync(0xffffffffu, sg, 2);
                sg8 += __shfl_xor_sync(0xffffffffu, sg8, 1);
                sg8 += __shfl_xor_sync(0xffffffffu, sg8, 2);
                if (tig == 0) {
                    float bb4 = b4f[0];
                    int base = tile * 128 + poff;
                    out[base + g]     = tanhf(sg + bb4);
                    out[base + g + 8] = tanhf(sg8 + bb4);
                }
            }
        }
    }
}

// ---------------- launch ----------------
extern "C" void kernel_launch(void* const* d_in, const int* in_sizes, int n_in,
                              void* d_out, int out_size)
{
    const float* x    = (const float*)d_in[0];
    const float* cb0  = (const float*)d_in[1];
    const float* ind0 = (const float*)d_in[2];
    const float* cb1  = (const float*)d_in[3];
    const float* ind1 = (const float*)d_in[4];
    const float* cb2  = (const float*)d_in[5];
    const float* ind2 = (const float*)d_in[6];
    const float* w0   = (const float*)d_in[7];
    const float* b0   = (const float*)d_in[8];
    const float* w1   = (const float*)d_in[9];
    const float* b1   = (const float*)d_in[10];
    const float* w2   = (const float*)d_in[11];
    const float* b2   = (const float*)d_in[12];
    const float* w3   = (const float*)d_in[13];
    const float* b3   = (const float*)d_in[14];
    const float* w4   = (const float*)d_in[15];
    const float* b4   = (const float*)d_in[16];

    int N = in_sizes[0] / 2;
    int ntiles = N / 128;

    static int configured = 0;
    if (!configured) {
        cudaFuncSetAttribute(mlp_tc_kernel,
                             cudaFuncAttributeMaxDynamicSharedMemorySize,
                             SMEM_BYTES);
        configured = 1;
    }

    prep_kernel<<<21, 256>>>(w0, w1, w2, w3, w4, b0, b1, b2, b3, b4,
                             ind0, cb0, ind1, cb1, ind2, cb2);
    mlp_tc_kernel<<<1184, 128, SMEM_BYTES>>>(x, (float*)d_out, ntiles);
}

// round 14
// speedup vs baseline: 1.0773x; 1.0773x over previous
#include <cuda_runtime.h>
#include <math.h>
#include <stdint.h>

typedef unsigned long long u64;

// ---------------- device-global scratch (no allocs allowed) ----------------
__device__ __align__(16) float  g_w0q[320];      // 5x64 quantized fp32
__device__ __align__(16) float  g_wk[3][4096];   // w1..w3 integer codes 0..63 ([k][j])
__device__ __align__(8)  float  g_qp[3][2];      // {scale, mn} per layer
__device__ __align__(16) float  g_w4q[64];
__device__ __align__(16) float  g_b0q[64];
__device__ __align__(16) float  g_bq[3][64];
__device__ __align__(16) float  g_b4q[4];
__device__ float4 g_grid0[128];
__device__ float4 g_grid1[512];
__device__ float4 g_grid2[2048];

// ---------------- packed helpers -------------------------------------------
__device__ __forceinline__ u64 pack2(float lo, float hi) {
    u64 r;
    asm("mov.b64 %0, {%1, %2};" : "=l"(r) : "f"(lo), "f"(hi));
    return r;
}
__device__ __forceinline__ void unpack2(u64 v, float& lo, float& hi) {
    asm("mov.b64 {%0, %1}, %2;" : "=f"(lo), "=f"(hi) : "l"(v));
}
__device__ __forceinline__ u64 fma2(u64 a, u64 b, u64 c) {
    u64 d;
    asm("fma.rn.f32x2 %0, %1, %2, %3;" : "=l"(d) : "l"(a), "l"(b), "l"(c));
    return d;
}
__device__ __forceinline__ u64 mul2(u64 a, u64 b) {
    u64 d;
    asm("mul.rn.f32x2 %0, %1, %2;" : "=l"(d) : "l"(a), "l"(b));
    return d;
}
__device__ __forceinline__ u64 add2(u64 a, u64 b) {
    u64 d;
    asm("add.rn.f32x2 %0, %1, %2;" : "=l"(d) : "l"(a), "l"(b));
    return d;
}
__device__ __forceinline__ u64 dup2(float c) { return pack2(c, c); }
__device__ __forceinline__ float rcp_fast(float x) {
    float r; asm("rcp.approx.f32 %0, %1;" : "=f"(r) : "f"(x)); return r;
}
__device__ __forceinline__ float ex2_fast(float x) {
    float r; asm("ex2.approx.f32 %0, %1;" : "=f"(r) : "f"(x)); return r;
}
__device__ __forceinline__ u64 rcp2(u64 a) {
    float l, h; unpack2(a, l, h); return pack2(rcp_fast(l), rcp_fast(h));
}
__device__ __forceinline__ u64 ex22(u64 a) {
    float l, h; unpack2(a, l, h); return pack2(ex2_fast(l), ex2_fast(h));
}
__device__ __forceinline__ uint32_t tf32_rna(float x) {
    uint32_t r;
    asm("cvt.rna.tf32.f32 %0, %1;" : "=r"(r) : "f"(x));
    return r;
}

// packed GELU (A&S 7.1.26, |erf err| <= 1.5e-7), sign-free tail:
// gelu(x) = 0.5x + |0.5x| * erf(|x|/sqrt2)
__device__ __forceinline__ u64 gelu2p(u64 v) {
    const u64 ABS2 = 0x7fffffff7fffffffULL;
    u64 ONE2 = dup2(1.0f);
    u64 ax = v & ABS2;
    u64 z  = mul2(ax, dup2(0.70710678118654752f));
    u64 t  = rcp2(fma2(z, dup2(0.3275911f), ONE2));
    u64 q  = fma2(dup2(-1.061405429f), t, dup2(1.453152027f));
    q = fma2(q, t, dup2(-1.421413741f));
    q = fma2(q, t, dup2(0.284496736f));
    q = fma2(q, t, dup2(-0.254829592f));
    u64 s  = mul2(q, t);
    u64 z2 = mul2(z, z);
    u64 e  = ex22(mul2(z2, dup2(-1.4426950408889634f)));
    u64 ea = fma2(s, e, ONE2);              // erf(|x|/sqrt2)
    u64 hx  = mul2(v,  dup2(0.5f));
    u64 ahx = mul2(ax, dup2(0.5f));
    return fma2(ahx, ea, hx);
}

// tf32 tensor-core mma (base PTX, sm_80+): D += A x B  (m16n8k8)
__device__ __forceinline__ void mma_tf32(float d[4], const uint32_t a[4],
                                         uint32_t b0, uint32_t b1) {
    asm volatile(
        "mma.sync.aligned.m16n8k8.row.col.f32.tf32.tf32.f32 "
        "{%0,%1,%2,%3}, {%4,%5,%6,%7}, {%8,%9}, {%0,%1,%2,%3};"
        : "+f"(d[0]), "+f"(d[1]), "+f"(d[2]), "+f"(d[3])
        : "r"(a[0]), "r"(a[1]), "r"(a[2]), "r"(a[3]), "r"(b0), "r"(b1));
}

// ---------------- merged prep: quantization + grid tables -------------------
__global__ void prep_kernel(const float* w0, const float* w1, const float* w2,
                            const float* w3, const float* w4,
                            const float* b0, const float* b1, const float* b2,
                            const float* b3, const float* b4,
                            const float* ind0, const float* cb0,
                            const float* ind1, const float* cb1,
                            const float* ind2, const float* cb2)
{
    int t = threadIdx.x;
    if (blockIdx.x >= 10) {
        int idx = (blockIdx.x - 10) * 256 + t;
        const float* ind; const float* cb; float4* dst; int row;
        if (idx < 128)       { ind = ind0; cb = cb0; dst = g_grid0; row = idx; }
        else if (idx < 640)  { ind = ind1; cb = cb1; dst = g_grid1; row = idx - 128; }
        else if (idx < 2688) { ind = ind2; cb = cb2; dst = g_grid2; row = idx - 640; }
        else return;
        const float* r = ind + (long)row * 64;
        float best = r[0]; int arg = 0;
        #pragma unroll
        for (int j = 1; j < 64; j++) {
            float v = r[j];
            if (v > best) { best = v; arg = j; }   // strict > == first-occurrence
        }
        dst[row] = make_float4(cb[arg * 4 + 0], cb[arg * 4 + 1],
                               cb[arg * 4 + 2], cb[arg * 4 + 3]);
        return;
    }

    __shared__ float smin[256], smax[256];
    const float* src; float* dst; int n; int kcode = 0;
    switch (blockIdx.x) {
        case 0: src = w0; dst = g_w0q;   n = 320;  break;
        case 1: src = w1; dst = g_wk[0]; n = 4096; kcode = 1; break;
        case 2: src = w2; dst = g_wk[1]; n = 4096; kcode = 1; break;
        case 3: src = w3; dst = g_wk[2]; n = 4096; kcode = 1; break;
        case 4: src = w4; dst = g_w4q;   n = 64;   break;
        case 5: src = b0; dst = g_b0q;   n = 64;   break;
        case 6: src = b1; dst = g_bq[0]; n = 64;   break;
        case 7: src = b2; dst = g_bq[1]; n = 64;   break;
        case 8: src = b3; dst = g_bq[2]; n = 64;   break;
        default: src = b4; dst = g_b4q;  n = 1;    break;
    }
    float mn = INFINITY, mx = -INFINITY;
    for (int i = t; i < n; i += 256) {
        float v = src[i];
        mn = fminf(mn, v); mx = fmaxf(mx, v);
    }
    smin[t] = mn; smax[t] = mx;
    __syncthreads();
    for (int s = 128; s > 0; s >>= 1) {
        if (t < s) {
            smin[t] = fminf(smin[t], smin[t + s]);
            smax[t] = fmaxf(smax[t], smax[t + s]);
        }
        __syncthreads();
    }
    mn = smin[0]; mx = smax[0];
    float scale = fmaxf(mx - mn, 1e-8f) / 63.0f;
    if (kcode) {
        for (int i = t; i < n; i += 256)
            dst[i] = rintf((src[i] - mn) / scale);   // integer code 0..63
        if (t == 0) {
            g_qp[blockIdx.x - 1][0] = scale;
            g_qp[blockIdx.x - 1][1] = mn;
        }
    } else {
        for (int i = t; i < n; i += 256)
            dst[i] = rintf((src[i] - mn) / scale) * scale + mn;
    }
}

// ---------------- main tensor-core kernel -----------------------------------
// R12 base (packed gelu, ones-MMA S, uint2 B-frags, sigma row permutation)
// + layer 0 moved onto the MMA: m16n8k8 natural layout, A cols tig / tig+4
// (features 0..4, zero-padded to 8), w0 staged as tf32 B fragments. No sigma
// needed for layer 0 — its D layout matches the other layers', epilogue
// unchanged.
//
// smem (bytes):
//   0     : wf  — B codes [3l][8kt][8nt][32 lanes] x uint2 = 49152
//   49152 : wf0 — layer0 B frags [8nt][32 lanes] x uint2 = 2048
//   51200 : b0s[64f], 51456: bz[3][64f], 52224: w4s[64f],
//   52480 : b4f[4f], 52496: qp[8f], 52528: in5s[5][128f]
#define OFF_WF    0
#define OFF_W0F   49152
#define OFF_B0S   51200
#define OFF_BZ    51456
#define OFF_W4S   52224
#define OFF_B4F   52480
#define OFF_QP    52496
#define OFF_IN5   52528
#define SMEM_BYTES 55088

__global__ void __launch_bounds__(128, 4)
mlp_tc_kernel(const float* __restrict__ x, float* __restrict__ out, int ntiles)
{
    extern __shared__ char smp[];
    const uint2* wf  = (const uint2*)(smp + OFF_WF);
    const uint2* wf0 = (const uint2*)(smp + OFF_W0F);
    float* b0s = (float*)(smp + OFF_B0S);
    float* bz  = (float*)(smp + OFF_BZ);
    float* w4s = (float*)(smp + OFF_W4S);
    float* b4f = (float*)(smp + OFF_B4F);
    float* qps = (float*)(smp + OFF_QP);
    float* in5s = (float*)(smp + OFF_IN5);

    int t = threadIdx.x;
    int wid = t >> 5;
    int lane = t & 31;
    int g = lane >> 2;      // row group 0..7
    int tig = lane & 3;     // thread-in-group

    const uint32_t ONEB = 0x3f800000u;   // 1.0f bits (exact tf32)

    // ---- one-time staging ----
    {
        uint2* wfw = (uint2*)(smp + OFF_WF);
        for (int e = t; e < 6144; e += 128) {
            int el = e & 31, nt = (e >> 5) & 7, kt = (e >> 8) & 7, l = e >> 11;
            int eg = el >> 2, etig = el & 3;
            int j = 8 * nt + eg;
            int k0 = 8 * kt + 2 * etig;
            const float* wl = g_wk[l];
            // b0 = K[8kt+2tig] (phys row tig), b1 = K[8kt+2tig+1] (phys tig+4)
            wfw[e] = make_uint2(__float_as_uint(wl[k0 * 64 + j]),
                                __float_as_uint(wl[(k0 + 1) * 64 + j]));
        }
        // layer0 B frags (natural m16n8k8 layout, tf32-rounded):
        // b0 = w0[k=etig][j], b1 = w0[k=etig+4][j] (k>=5 -> 0)
        uint2* wf0w = (uint2*)(smp + OFF_W0F);
        for (int e = t; e < 256; e += 128) {
            int el = e & 31, nt = e >> 5;
            int eg = el >> 2, etig = el & 3;
            int j = 8 * nt + eg;
            uint32_t b0v = tf32_rna(g_w0q[etig * 64 + j]);
            uint32_t b1v = (etig == 0) ? tf32_rna(g_w0q[4 * 64 + j]) : 0u;
            wf0w[e] = make_uint2(b0v, b1v);
        }
    }
    if (t < 64) {
        b0s[t] = g_b0q[t];
        bz[t] = g_bq[0][t]; bz[64 + t] = g_bq[1][t]; bz[128 + t] = g_bq[2][t];
        w4s[t] = g_w4q[t];
        if (t == 0) b4f[0] = g_b4q[0];
        if (t < 6) qps[t] = ((const float*)g_qp)[t];
    }

    for (int tile = blockIdx.x; tile < ntiles; tile += gridDim.x) {
        __syncthreads();

        // ---- interp: one point per thread -> in5s[5][128] ----
        int gidx = tile * 128 + t;
        {
            float2 xv = __ldg((const float2*)x + gidx);
            float feat = xv.x;
            float tc = (xv.y + 1.0f) * 0.5f;
            float4 gg = make_float4(0.f, 0.f, 0.f, 0.f);
            auto interp_add = [&](const float4* __restrict__ tab, int res) {
                float c = tc * (float)(res - 1);
                int left  = min((int)floorf(c), res - 2);
                int right = max((int)ceilf(c), 1);
                float w = c - (float)left;
                float4 gl = __ldg(tab + left);
                float4 gr = __ldg(tab + right);
                gg.x += (1.0f - w) * gl.x + w * gr.x;
                gg.y += (1.0f - w) * gl.y + w * gr.y;
                gg.z += (1.0f - w) * gl.z + w * gr.z;
                gg.w += (1.0f - w) * gl.w + w * gr.w;
            };
            interp_add(g_grid0, 128);
            interp_add(g_grid1, 512);
            interp_add(g_grid2, 2048);
            in5s[0 * 128 + t] = gg.x;
            in5s[1 * 128 + t] = gg.y;
            in5s[2 * 128 + t] = gg.z;
            in5s[3 * 128 + t] = gg.w;
            in5s[4 * 128 + t] = feat;
        }
        __syncthreads();

        // ---- each warp: 2 sequential m16 sub-tiles ----
        #pragma unroll 1
        for (int s = 0; s < 2; s++) {
            int mt = wid + 4 * s;
            int poff = mt * 16;

            float d[8][4];
            float d8[4];                 // S fragment: A @ ones
            uint32_t A[8][4];            // tf32 A fragments (one per kt)

            // ---- layer 0 (5 -> 64) via MMA (natural k8 layout) ----
            {
                uint32_t A0[4];
                A0[0] = tf32_rna(in5s[tig * 128 + poff + g]);
                A0[1] = tf32_rna(in5s[tig * 128 + poff + g + 8]);
                if (tig == 0) {
                    A0[2] = tf32_rna(in5s[4 * 128 + poff + g]);
                    A0[3] = tf32_rna(in5s[4 * 128 + poff + g + 8]);
                } else {
                    A0[2] = 0u; A0[3] = 0u;
                }
                #pragma unroll
                for (int nt = 0; nt < 8; nt++) {
                    d[nt][0] = 0.f; d[nt][1] = 0.f;
                    d[nt][2] = 0.f; d[nt][3] = 0.f;
                }
                #pragma unroll
                for (int nt = 0; nt < 8; nt++) {
                    uint2 B = wf0[nt * 32 + lane];
                    mma_tf32(d[nt], A0, B.x, B.y);
                }
            }

            // ---- epilogue: scale*d + bias + off -> gelu -> tf32 A fragments
            auto epi = [&](const float* bias, float scl, float offa, float offb) {
                u64 scl2 = dup2(scl);
                u64 offa2 = dup2(offa);
                u64 offb2 = dup2(offb);
                #pragma unroll
                for (int nt = 0; nt < 8; nt++) {
                    int f0 = 8 * nt + 2 * tig;
                    u64 bb2 = *(const u64*)(bias + f0);
                    u64 a01 = add2(fma2(scl2, pack2(d[nt][0], d[nt][1]), bb2),
                                   offa2);
                    u64 a23 = add2(fma2(scl2, pack2(d[nt][2], d[nt][3]), bb2),
                                   offb2);
                    u64 p01 = gelu2p(a01);
                    u64 p23 = gelu2p(a23);
                    float g0, g1, g2, g3;
                    unpack2(p01, g0, g1);
                    unpack2(p23, g2, g3);
                    // D->A renaming: a0=d0(row g,col 2tig), a1=d2(row g+8),
                    //                a2=d1(col 2tig+1),      a3=d3
                    A[nt][0] = tf32_rna(g0);
                    A[nt][1] = tf32_rna(g2);
                    A[nt][2] = tf32_rna(g1);
                    A[nt][3] = tf32_rna(g3);
                }
            };
            epi(b0s, 1.0f, 0.f, 0.f);

            // ---- 3 mma layers (single tf32 product + ones-column for S) ----
            float scl3 = 0.f, offa3 = 0.f, offb3 = 0.f;
            #pragma unroll 1
            for (int l = 0; l < 3; l++) {
                #pragma unroll
                for (int nt = 0; nt < 8; nt++) {
                    d[nt][0] = 0.f; d[nt][1] = 0.f;
                    d[nt][2] = 0.f; d[nt][3] = 0.f;
                }
                d8[0] = 0.f; d8[1] = 0.f; d8[2] = 0.f; d8[3] = 0.f;
                const uint2* wfl = wf + (size_t)l * 8 * 8 * 32;
                #pragma unroll
                for (int kt = 0; kt < 8; kt++) {
                    #pragma unroll
                    for (int nt = 0; nt < 8; nt++) {
                        uint2 B = wfl[(kt * 8 + nt) * 32 + lane];
                        mma_tf32(d[nt], A[kt], B.x, B.y);
                    }
                    mma_tf32(d8, A[kt], ONEB, ONEB);   // S accumulation
                }
                float scl = qps[2 * l], mn = qps[2 * l + 1];
                if (l < 2) epi(bz + 64 * l, scl, mn * d8[0], mn * d8[2]);
                else { scl3 = scl; offa3 = mn * d8[0]; offb3 = mn * d8[2]; }
            }

            // ---- final: scale/offset + bias b3, gelu, dot w4, reduce, tanh --
            {
                const float* b3 = bz + 128;
                u64 scl2 = dup2(scl3);
                u64 offa2 = dup2(offa3);
                u64 offb2 = dup2(offb3);
                u64 dg = pack2(0.f, 0.f), dg8 = pack2(0.f, 0.f);
                #pragma unroll
                for (int nt = 0; nt < 8; nt++) {
                    int f0 = 8 * nt + 2 * tig;
                    u64 bb2 = *(const u64*)(b3 + f0);
                    u64 a01 = add2(fma2(scl2, pack2(d[nt][0], d[nt][1]), bb2),
                                   offa2);
                    u64 a23 = add2(fma2(scl2, pack2(d[nt][2], d[nt][3]), bb2),
                                   offb2);
                    u64 w4p = *(const u64*)(w4s + f0);
                    dg  = fma2(gelu2p(a01), w4p, dg);
                    dg8 = fma2(gelu2p(a23), w4p, dg8);
                }
                float a, b, sg, sg8;
                unpack2(dg, a, b);  sg  = a + b;
                unpack2(dg8, a, b); sg8 = a + b;
                sg  += __shfl_xor_sync(0xffffffffu, sg, 1);
                sg  += __shfl_xor_sync(0xffffffffu, sg, 2);
                sg8 += __shfl_xor_sync(0xffffffffu, sg8, 1);
                sg8 += __shfl_xor_sync(0xffffffffu, sg8, 2);
                if (tig == 0) {
                    float bb4 = b4f[0];
                    int base = tile * 128 + poff;
                    out[base + g]     = tanhf(sg + bb4);
                    out[base + g + 8] = tanhf(sg8 + bb4);
                }
            }
        }
    }
}

// ---------------- launch ----------------
extern "C" void kernel_launch(void* const* d_in, const int* in_sizes, int n_in,
                              void* d_out, int out_size)
{
    const float* x    = (const float*)d_in[0];
    const float* cb0  = (const float*)d_in[1];
    const float* ind0 = (const float*)d_in[2];
    const float* cb1  = (const float*)d_in[3];
    const float* ind1 = (const float*)d_in[4];
    const float* cb2  = (const float*)d_in[5];
    const float* ind2 = (const float*)d_in[6];
    const float* w0   = (const float*)d_in[7];
    const float* b0   = (const float*)d_in[8];
    const float* w1   = (const float*)d_in[9];
    const float* b1   = (const float*)d_in[10];
    const float* w2   = (const float*)d_in[11];
    const float* b2   = (const float*)d_in[12];
    const float* w3   = (const float*)d_in[13];
    const float* b3   = (const float*)d_in[14];
    const float* w4   = (const float*)d_in[15];
    const float* b4   = (const float*)d_in[16];

    int N = in_sizes[0] / 2;
    int ntiles = N / 128;

    static int configured = 0;
    if (!configured) {
        cudaFuncSetAttribute(mlp_tc_kernel,
                             cudaFuncAttributeMaxDynamicSharedMemorySize,
                             SMEM_BYTES);
        configured = 1;
    }

    prep_kernel<<<21, 256>>>(w0, w1, w2, w3, w4, b0, b1, b2, b3, b4,
                             ind0, cb0, ind1, cb1, ind2, cb2);
    mlp_tc_kernel<<<1184, 128, SMEM_BYTES>>>(x, (float*)d_out, ntiles);
}

// round 15
// speedup vs baseline: 1.1991x; 1.1131x over previous
#include <cuda_runtime.h>
#include <math.h>
#include <stdint.h>

typedef unsigned long long u64;

// ---------------- device-global scratch (no allocs allowed) ----------------
__device__ __align__(16) float  g_w0q[320];      // 5x64 quantized fp32
__device__ __align__(16) float  g_wk[3][4096];   // w1..w3 integer codes 0..63 ([k][j])
__device__ __align__(8)  float  g_qp[3][2];      // {scale, mn} per layer
__device__ __align__(16) float  g_w4q[64];
__device__ __align__(16) float  g_b0q[64];
__device__ __align__(16) float  g_bq[3][64];
__device__ __align__(16) float  g_b4q[4];
__device__ float4 g_grid0[128];
__device__ float4 g_grid1[512];
__device__ float4 g_grid2[2048];

// ---------------- packed helpers -------------------------------------------
__device__ __forceinline__ u64 pack2(float lo, float hi) {
    u64 r;
    asm("mov.b64 %0, {%1, %2};" : "=l"(r) : "f"(lo), "f"(hi));
    return r;
}
__device__ __forceinline__ void unpack2(u64 v, float& lo, float& hi) {
    asm("mov.b64 {%0, %1}, %2;" : "=f"(lo), "=f"(hi) : "l"(v));
}
__device__ __forceinline__ u64 fma2(u64 a, u64 b, u64 c) {
    u64 d;
    asm("fma.rn.f32x2 %0, %1, %2, %3;" : "=l"(d) : "l"(a), "l"(b), "l"(c));
    return d;
}
__device__ __forceinline__ u64 mul2(u64 a, u64 b) {
    u64 d;
    asm("mul.rn.f32x2 %0, %1, %2;" : "=l"(d) : "l"(a), "l"(b));
    return d;
}
__device__ __forceinline__ u64 add2(u64 a, u64 b) {
    u64 d;
    asm("add.rn.f32x2 %0, %1, %2;" : "=l"(d) : "l"(a), "l"(b));
    return d;
}
__device__ __forceinline__ u64 dup2(float c) { return pack2(c, c); }
__device__ __forceinline__ float rcp_fast(float x) {
    float r; asm("rcp.approx.f32 %0, %1;" : "=f"(r) : "f"(x)); return r;
}
__device__ __forceinline__ float ex2_fast(float x) {
    float r; asm("ex2.approx.f32 %0, %1;" : "=f"(r) : "f"(x)); return r;
}
__device__ __forceinline__ u64 rcp2(u64 a) {
    float l, h; unpack2(a, l, h); return pack2(rcp_fast(l), rcp_fast(h));
}
__device__ __forceinline__ u64 ex22(u64 a) {
    float l, h; unpack2(a, l, h); return pack2(ex2_fast(l), ex2_fast(h));
}
__device__ __forceinline__ uint32_t tf32_rna(float x) {
    uint32_t r;
    asm("cvt.rna.tf32.f32 %0, %1;" : "=r"(r) : "f"(x));
    return r;
}

// packed DOUBLED GELU, A&S 7.1.25 3-term (|erf err| <= 2.5e-5, validated R13):
// returns 2*gelu(x) = x + |x|*erf(|x|/sqrt2). The factor 2 is compensated
// exactly by halving the staged scale/mn/w4 (linearity).
__device__ __forceinline__ u64 gelu2x(u64 v) {
    const u64 ABS2 = 0x7fffffff7fffffffULL;
    u64 ONE2 = dup2(1.0f);
    u64 ax = v & ABS2;
    // t = 1/(1 + 0.47047*|x|/sqrt2)
    u64 t  = rcp2(fma2(ax, dup2(0.33267982f), ONE2));
    // s = -(a1*t + a2*t^2 + a3*t^3), a1=0.3480242, a2=-0.0958798, a3=0.7478556
    u64 q  = fma2(dup2(-0.7478556f), t, dup2(0.0958798f));
    q = fma2(q, t, dup2(-0.3480242f));
    u64 s  = mul2(q, t);
    // e = exp(-x^2/2) via ex2(x^2 * -0.5*log2e)
    u64 x2 = mul2(ax, ax);
    u64 e  = ex22(mul2(x2, dup2(-0.7213475204f)));
    u64 ea = fma2(s, e, ONE2);              // erf(|x|/sqrt2)
    return fma2(ax, ea, v);                 // x + |x|*erf = 2*gelu(x)
}

// tf32 tensor-core mma (base PTX, sm_80+): D += A x B  (m16n8k8)
__device__ __forceinline__ void mma_tf32(float d[4], const uint32_t a[4],
                                         uint32_t b0, uint32_t b1) {
    asm volatile(
        "mma.sync.aligned.m16n8k8.row.col.f32.tf32.tf32.f32 "
        "{%0,%1,%2,%3}, {%4,%5,%6,%7}, {%8,%9}, {%0,%1,%2,%3};"
        : "+f"(d[0]), "+f"(d[1]), "+f"(d[2]), "+f"(d[3])
        : "r"(a[0]), "r"(a[1]), "r"(a[2]), "r"(a[3]), "r"(b0), "r"(b1));
}

// ---------------- merged prep: quantization + grid tables -------------------
__global__ void prep_kernel(const float* w0, const float* w1, const float* w2,
                            const float* w3, const float* w4,
                            const float* b0, const float* b1, const float* b2,
                            const float* b3, const float* b4,
                            const float* ind0, const float* cb0,
                            const float* ind1, const float* cb1,
                            const float* ind2, const float* cb2)
{
    int t = threadIdx.x;
    if (blockIdx.x >= 10) {
        int idx = (blockIdx.x - 10) * 256 + t;
        const float* ind; const float* cb; float4* dst; int row;
        if (idx < 128)       { ind = ind0; cb = cb0; dst = g_grid0; row = idx; }
        else if (idx < 640)  { ind = ind1; cb = cb1; dst = g_grid1; row = idx - 128; }
        else if (idx < 2688) { ind = ind2; cb = cb2; dst = g_grid2; row = idx - 640; }
        else return;
        const float* r = ind + (long)row * 64;
        float best = r[0]; int arg = 0;
        #pragma unroll
        for (int j = 1; j < 64; j++) {
            float v = r[j];
            if (v > best) { best = v; arg = j; }   // strict > == first-occurrence
        }
        dst[row] = make_float4(cb[arg * 4 + 0], cb[arg * 4 + 1],
                               cb[arg * 4 + 2], cb[arg * 4 + 3]);
        return;
    }

    __shared__ float smin[256], smax[256];
    const float* src; float* dst; int n; int kcode = 0;
    switch (blockIdx.x) {
        case 0: src = w0; dst = g_w0q;   n = 320;  break;
        case 1: src = w1; dst = g_wk[0]; n = 4096; kcode = 1; break;
        case 2: src = w2; dst = g_wk[1]; n = 4096; kcode = 1; break;
        case 3: src = w3; dst = g_wk[2]; n = 4096; kcode = 1; break;
        case 4: src = w4; dst = g_w4q;   n = 64;   break;
        case 5: src = b0; dst = g_b0q;   n = 64;   break;
        case 6: src = b1; dst = g_bq[0]; n = 64;   break;
        case 7: src = b2; dst = g_bq[1]; n = 64;   break;
        case 8: src = b3; dst = g_bq[2]; n = 64;   break;
        default: src = b4; dst = g_b4q;  n = 1;    break;
    }
    float mn = INFINITY, mx = -INFINITY;
    for (int i = t; i < n; i += 256) {
        float v = src[i];
        mn = fminf(mn, v); mx = fmaxf(mx, v);
    }
    smin[t] = mn; smax[t] = mx;
    __syncthreads();
    for (int s = 128; s > 0; s >>= 1) {
        if (t < s) {
            smin[t] = fminf(smin[t], smin[t + s]);
            smax[t] = fmaxf(smax[t], smax[t + s]);
        }
        __syncthreads();
    }
    mn = smin[0]; mx = smax[0];
    float scale = fmaxf(mx - mn, 1e-8f) / 63.0f;
    if (kcode) {
        for (int i = t; i < n; i += 256)
            dst[i] = rintf((src[i] - mn) / scale);   // integer code 0..63
        if (t == 0) {
            g_qp[blockIdx.x - 1][0] = scale;
            g_qp[blockIdx.x - 1][1] = mn;
        }
    } else {
        for (int i = t; i < n; i += 256)
            dst[i] = rintf((src[i] - mn) / scale) * scale + mn;
    }
}

// ---------------- main tensor-core kernel -----------------------------------
// R14 base (layer0 on MMA, ones-MMA S, uint2 B-frags, sigma row permutation)
// + doubled-gelu folding: gelu2x returns 2*gelu; staged qps (scale,mn) and
// w4s are halved to compensate exactly.
//
// smem (bytes):
//   0     : wf  — B codes [3l][8kt][8nt][32 lanes] x uint2 = 49152
//   49152 : wf0 — layer0 B frags [8nt][32 lanes] x uint2 = 2048
//   51200 : b0s[64f], 51456: bz[3][64f], 52224: w4s[64f],
//   52480 : b4f[4f], 52496: qp[8f], 52528: in5s[5][128f]
#define OFF_WF    0
#define OFF_W0F   49152
#define OFF_B0S   51200
#define OFF_BZ    51456
#define OFF_W4S   52224
#define OFF_B4F   52480
#define OFF_QP    52496
#define OFF_IN5   52528
#define SMEM_BYTES 55088

__global__ void __launch_bounds__(128, 4)
mlp_tc_kernel(const float* __restrict__ x, float* __restrict__ out, int ntiles)
{
    extern __shared__ char smp[];
    const uint2* wf  = (const uint2*)(smp + OFF_WF);
    const uint2* wf0 = (const uint2*)(smp + OFF_W0F);
    float* b0s = (float*)(smp + OFF_B0S);
    float* bz  = (float*)(smp + OFF_BZ);
    float* w4s = (float*)(smp + OFF_W4S);
    float* b4f = (float*)(smp + OFF_B4F);
    float* qps = (float*)(smp + OFF_QP);
    float* in5s = (float*)(smp + OFF_IN5);

    int t = threadIdx.x;
    int wid = t >> 5;
    int lane = t & 31;
    int g = lane >> 2;      // row group 0..7
    int tig = lane & 3;     // thread-in-group

    const uint32_t ONEB = 0x3f800000u;   // 1.0f bits (exact tf32)

    // ---- one-time staging ----
    {
        uint2* wfw = (uint2*)(smp + OFF_WF);
        for (int e = t; e < 6144; e += 128) {
            int el = e & 31, nt = (e >> 5) & 7, kt = (e >> 8) & 7, l = e >> 11;
            int eg = el >> 2, etig = el & 3;
            int j = 8 * nt + eg;
            int k0 = 8 * kt + 2 * etig;
            const float* wl = g_wk[l];
            // b0 = K[8kt+2tig] (phys row tig), b1 = K[8kt+2tig+1] (phys tig+4)
            wfw[e] = make_uint2(__float_as_uint(wl[k0 * 64 + j]),
                                __float_as_uint(wl[(k0 + 1) * 64 + j]));
        }
        // layer0 B frags (natural m16n8k8 layout, tf32-rounded):
        uint2* wf0w = (uint2*)(smp + OFF_W0F);
        for (int e = t; e < 256; e += 128) {
            int el = e & 31, nt = e >> 5;
            int eg = el >> 2, etig = el & 3;
            int j = 8 * nt + eg;
            uint32_t b0v = tf32_rna(g_w0q[etig * 64 + j]);
            uint32_t b1v = (etig == 0) ? tf32_rna(g_w0q[4 * 64 + j]) : 0u;
            wf0w[e] = make_uint2(b0v, b1v);
        }
    }
    if (t < 64) {
        b0s[t] = g_b0q[t];
        bz[t] = g_bq[0][t]; bz[64 + t] = g_bq[1][t]; bz[128 + t] = g_bq[2][t];
        w4s[t] = 0.5f * g_w4q[t];               // halved: inputs are 2*gelu
        if (t == 0) b4f[0] = g_b4q[0];
        if (t < 6) qps[t] = 0.5f * ((const float*)g_qp)[t];  // halved scale & mn
    }

    for (int tile = blockIdx.x; tile < ntiles; tile += gridDim.x) {
        __syncthreads();

        // ---- interp: one point per thread -> in5s[5][128] ----
        int gidx = tile * 128 + t;
        {
            float2 xv = __ldg((const float2*)x + gidx);
            float feat = xv.x;
            float tc = (xv.y + 1.0f) * 0.5f;
            float4 gg = make_float4(0.f, 0.f, 0.f, 0.f);
            auto interp_add = [&](const float4* __restrict__ tab, int res) {
                float c = tc * (float)(res - 1);
                int left  = min((int)floorf(c), res - 2);
                int right = max((int)ceilf(c), 1);
                float w = c - (float)left;
                float4 gl = __ldg(tab + left);
                float4 gr = __ldg(tab + right);
                gg.x += (1.0f - w) * gl.x + w * gr.x;
                gg.y += (1.0f - w) * gl.y + w * gr.y;
                gg.z += (1.0f - w) * gl.z + w * gr.z;
                gg.w += (1.0f - w) * gl.w + w * gr.w;
            };
            interp_add(g_grid0, 128);
            interp_add(g_grid1, 512);
            interp_add(g_grid2, 2048);
            in5s[0 * 128 + t] = gg.x;
            in5s[1 * 128 + t] = gg.y;
            in5s[2 * 128 + t] = gg.z;
            in5s[3 * 128 + t] = gg.w;
            in5s[4 * 128 + t] = feat;
        }
        __syncthreads();

        // ---- each warp: 2 sequential m16 sub-tiles ----
        #pragma unroll 1
        for (int s = 0; s < 2; s++) {
            int mt = wid + 4 * s;
            int poff = mt * 16;

            float d[8][4];
            float d8[4];                 // S fragment: A @ ones
            uint32_t A[8][4];            // tf32 A fragments (one per kt)

            // ---- layer 0 (5 -> 64) via MMA (natural k8 layout) ----
            {
                uint32_t A0[4];
                A0[0] = tf32_rna(in5s[tig * 128 + poff + g]);
                A0[1] = tf32_rna(in5s[tig * 128 + poff + g + 8]);
                if (tig == 0) {
                    A0[2] = tf32_rna(in5s[4 * 128 + poff + g]);
                    A0[3] = tf32_rna(in5s[4 * 128 + poff + g + 8]);
                } else {
                    A0[2] = 0u; A0[3] = 0u;
                }
                #pragma unroll
                for (int nt = 0; nt < 8; nt++) {
                    d[nt][0] = 0.f; d[nt][1] = 0.f;
                    d[nt][2] = 0.f; d[nt][3] = 0.f;
                }
                #pragma unroll
                for (int nt = 0; nt < 8; nt++) {
                    uint2 B = wf0[nt * 32 + lane];
                    mma_tf32(d[nt], A0, B.x, B.y);
                }
            }

            // ---- epilogue: scale*d + bias + off -> 2*gelu -> tf32 A frags ---
            auto epi = [&](const float* bias, float scl, float offa, float offb) {
                u64 scl2 = dup2(scl);
                u64 offa2 = dup2(offa);
                u64 offb2 = dup2(offb);
                #pragma unroll
                for (int nt = 0; nt < 8; nt++) {
                    int f0 = 8 * nt + 2 * tig;
                    u64 bb2 = *(const u64*)(bias + f0);
                    u64 a01 = add2(fma2(scl2, pack2(d[nt][0], d[nt][1]), bb2),
                                   offa2);
                    u64 a23 = add2(fma2(scl2, pack2(d[nt][2], d[nt][3]), bb2),
                                   offb2);
                    u64 p01 = gelu2x(a01);
                    u64 p23 = gelu2x(a23);
                    float g0, g1, g2, g3;
                    unpack2(p01, g0, g1);
                    unpack2(p23, g2, g3);
                    // D->A renaming: a0=d0(row g,col 2tig), a1=d2(row g+8),
                    //                a2=d1(col 2tig+1),      a3=d3
                    A[nt][0] = tf32_rna(g0);
                    A[nt][1] = tf32_rna(g2);
                    A[nt][2] = tf32_rna(g1);
                    A[nt][3] = tf32_rna(g3);
                }
            };
            epi(b0s, 1.0f, 0.f, 0.f);

            // ---- 3 mma layers (single tf32 product + ones-column for S) ----
            float scl3 = 0.f, offa3 = 0.f, offb3 = 0.f;
            #pragma unroll 1
            for (int l = 0; l < 3; l++) {
                #pragma unroll
                for (int nt = 0; nt < 8; nt++) {
                    d[nt][0] = 0.f; d[nt][1] = 0.f;
                    d[nt][2] = 0.f; d[nt][3] = 0.f;
                }
                d8[0] = 0.f; d8[1] = 0.f; d8[2] = 0.f; d8[3] = 0.f;
                const uint2* wfl = wf + (size_t)l * 8 * 8 * 32;
                #pragma unroll
                for (int kt = 0; kt < 8; kt++) {
                    #pragma unroll
                    for (int nt = 0; nt < 8; nt++) {
                        uint2 B = wfl[(kt * 8 + nt) * 32 + lane];
                        mma_tf32(d[nt], A[kt], B.x, B.y);
                    }
                    mma_tf32(d8, A[kt], ONEB, ONEB);   // S accumulation
                }
                float scl = qps[2 * l], mn = qps[2 * l + 1];   // pre-halved
                if (l < 2) epi(bz + 64 * l, scl, mn * d8[0], mn * d8[2]);
                else { scl3 = scl; offa3 = mn * d8[0]; offb3 = mn * d8[2]; }
            }

            // ---- final: scale/offset + bias b3, 2*gelu, dot w4/2, tanh ----
            {
                const float* b3 = bz + 128;
                u64 scl2 = dup2(scl3);
                u64 offa2 = dup2(offa3);
                u64 offb2 = dup2(offb3);
                u64 dg = pack2(0.f, 0.f), dg8 = pack2(0.f, 0.f);
                #pragma unroll
                for (int nt = 0; nt < 8; nt++) {
                    int f0 = 8 * nt + 2 * tig;
                    u64 bb2 = *(const u64*)(b3 + f0);
                    u64 a01 = add2(fma2(scl2, pack2(d[nt][0], d[nt][1]), bb2),
                                   offa2);
                    u64 a23 = add2(fma2(scl2, pack2(d[nt][2], d[nt][3]), bb2),
                                   offb2);
                    u64 w4p = *(const u64*)(w4s + f0);
                    dg  = fma2(gelu2x(a01), w4p, dg);
                    dg8 = fma2(gelu2x(a23), w4p, dg8);
                }
                float a, b, sg, sg8;
                unpack2(dg, a, b);  sg  = a + b;
                unpack2(dg8, a, b); sg8 = a + b;
                sg  += __shfl_xor_sync(0xffffffffu, sg, 1);
                sg  += __shfl_xor_sync(0xffffffffu, sg, 2);
                sg8 += __shfl_xor_sync(0xffffffffu, sg8, 1);
                sg8 += __shfl_xor_sync(0xffffffffu, sg8, 2);
                if (tig == 0) {
                    float bb4 = b4f[0];
                    int base = tile * 128 + poff;
                    out[base + g]     = tanhf(sg + bb4);
                    out[base + g + 8] = tanhf(sg8 + bb4);
                }
            }
        }
    }
}

// ---------------- launch ----------------
extern "C" void kernel_launch(void* const* d_in, const int* in_sizes, int n_in,
                              void* d_out, int out_size)
{
    const float* x    = (const float*)d_in[0];
    const float* cb0  = (const float*)d_in[1];
    const float* ind0 = (const float*)d_in[2];
    const float* cb1  = (const float*)d_in[3];
    const float* ind1 = (const float*)d_in[4];
    const float* cb2  = (const float*)d_in[5];
    const float* ind2 = (const float*)d_in[6];
    const float* w0   = (const float*)d_in[7];
    const float* b0   = (const float*)d_in[8];
    const float* w1   = (const float*)d_in[9];
    const float* b1   = (const float*)d_in[10];
    const float* w2   = (const float*)d_in[11];
    const float* b2   = (const float*)d_in[12];
    const float* w3   = (const float*)d_in[13];
    const float* b3   = (const float*)d_in[14];
    const float* w4   = (const float*)d_in[15];
    const float* b4   = (const float*)d_in[16];

    int N = in_sizes[0] / 2;
    int ntiles = N / 128;

    static int configured = 0;
    if (!configured) {
        cudaFuncSetAttribute(mlp_tc_kernel,
                             cudaFuncAttributeMaxDynamicSharedMemorySize,
                             SMEM_BYTES);
        configured = 1;
    }

    prep_kernel<<<21, 256>>>(w0, w1, w2, w3, w4, b0, b1, b2, b3, b4,
                             ind0, cb0, ind1, cb1, ind2, cb2);
    mlp_tc_kernel<<<1184, 128, SMEM_BYTES>>>(x, (float*)d_out, ntiles);
}

// round 16
// speedup vs baseline: 1.2682x; 1.0576x over previous
#include <cuda_runtime.h>
#include <math.h>
#include <stdint.h>

typedef unsigned long long u64;

// ---------------- device-global scratch (no allocs allowed) ----------------
__device__ __align__(16) float  g_w0q[320];      // 5x64 quantized fp32
__device__ __align__(16) float  g_wq[3][4096];   // w1..w3 quantized fp32 ([k][j])
__device__ __align__(16) float  g_w4q[64];
__device__ __align__(16) float  g_b0q[64];
__device__ __align__(16) float  g_bq[3][64];
__device__ __align__(16) float  g_b4q[4];
__device__ float4 g_grid0[128];
__device__ float4 g_grid1[512];
__device__ float4 g_grid2[2048];

// ---------------- packed helpers -------------------------------------------
__device__ __forceinline__ u64 pack2(float lo, float hi) {
    u64 r;
    asm("mov.b64 %0, {%1, %2};" : "=l"(r) : "f"(lo), "f"(hi));
    return r;
}
__device__ __forceinline__ void unpack2(u64 v, float& lo, float& hi) {
    asm("mov.b64 {%0, %1}, %2;" : "=f"(lo), "=f"(hi) : "l"(v));
}
__device__ __forceinline__ u64 fma2(u64 a, u64 b, u64 c) {
    u64 d;
    asm("fma.rn.f32x2 %0, %1, %2, %3;" : "=l"(d) : "l"(a), "l"(b), "l"(c));
    return d;
}
__device__ __forceinline__ u64 mul2(u64 a, u64 b) {
    u64 d;
    asm("mul.rn.f32x2 %0, %1, %2;" : "=l"(d) : "l"(a), "l"(b));
    return d;
}
__device__ __forceinline__ u64 add2(u64 a, u64 b) {
    u64 d;
    asm("add.rn.f32x2 %0, %1, %2;" : "=l"(d) : "l"(a), "l"(b));
    return d;
}
__device__ __forceinline__ u64 dup2(float c) { return pack2(c, c); }
__device__ __forceinline__ float rcp_fast(float x) {
    float r; asm("rcp.approx.f32 %0, %1;" : "=f"(r) : "f"(x)); return r;
}
__device__ __forceinline__ float ex2_fast(float x) {
    float r; asm("ex2.approx.f32 %0, %1;" : "=f"(r) : "f"(x)); return r;
}
__device__ __forceinline__ u64 rcp2(u64 a) {
    float l, h; unpack2(a, l, h); return pack2(rcp_fast(l), rcp_fast(h));
}
__device__ __forceinline__ u64 ex22(u64 a) {
    float l, h; unpack2(a, l, h); return pack2(ex2_fast(l), ex2_fast(h));
}
__device__ __forceinline__ uint32_t tf32_rna(float x) {
    uint32_t r;
    asm("cvt.rna.tf32.f32 %0, %1;" : "=r"(r) : "f"(x));
    return r;
}

// packed DOUBLED GELU, A&S 7.1.25 3-term (|erf err| <= 2.5e-5):
// returns 2*gelu(x) = x + |x|*erf(|x|/sqrt2); factor 2 compensated by
// halving staged weights (w1..w3, w4) exactly in prep/staging.
__device__ __forceinline__ u64 gelu2x(u64 v) {
    const u64 ABS2 = 0x7fffffff7fffffffULL;
    u64 ONE2 = dup2(1.0f);
    u64 ax = v & ABS2;
    u64 t  = rcp2(fma2(ax, dup2(0.33267982f), ONE2));
    u64 q  = fma2(dup2(-0.7478556f), t, dup2(0.0958798f));
    q = fma2(q, t, dup2(-0.3480242f));
    u64 s  = mul2(q, t);
    u64 x2 = mul2(ax, ax);
    u64 e  = ex22(mul2(x2, dup2(-0.7213475204f)));
    u64 ea = fma2(s, e, ONE2);              // erf(|x|/sqrt2)
    return fma2(ax, ea, v);                 // x + |x|*erf = 2*gelu(x)
}

// tf32 tensor-core mma (base PTX, sm_80+): D += A x B  (m16n8k8)
__device__ __forceinline__ void mma_tf32(float d[4], const uint32_t a[4],
                                         uint32_t b0, uint32_t b1) {
    asm volatile(
        "mma.sync.aligned.m16n8k8.row.col.f32.tf32.tf32.f32 "
        "{%0,%1,%2,%3}, {%4,%5,%6,%7}, {%8,%9}, {%0,%1,%2,%3};"
        : "+f"(d[0]), "+f"(d[1]), "+f"(d[2]), "+f"(d[3])
        : "r"(a[0]), "r"(a[1]), "r"(a[2]), "r"(a[3]), "r"(b0), "r"(b1));
}

// ---------------- merged prep: quantization + grid tables -------------------
__global__ void prep_kernel(const float* w0, const float* w1, const float* w2,
                            const float* w3, const float* w4,
                            const float* b0, const float* b1, const float* b2,
                            const float* b3, const float* b4,
                            const float* ind0, const float* cb0,
                            const float* ind1, const float* cb1,
                            const float* ind2, const float* cb2)
{
    int t = threadIdx.x;
    if (blockIdx.x >= 10) {
        int idx = (blockIdx.x - 10) * 256 + t;
        const float* ind; const float* cb; float4* dst; int row;
        if (idx < 128)       { ind = ind0; cb = cb0; dst = g_grid0; row = idx; }
        else if (idx < 640)  { ind = ind1; cb = cb1; dst = g_grid1; row = idx - 128; }
        else if (idx < 2688) { ind = ind2; cb = cb2; dst = g_grid2; row = idx - 640; }
        else return;
        const float* r = ind + (long)row * 64;
        float best = r[0]; int arg = 0;
        #pragma unroll
        for (int j = 1; j < 64; j++) {
            float v = r[j];
            if (v > best) { best = v; arg = j; }   // strict > == first-occurrence
        }
        dst[row] = make_float4(cb[arg * 4 + 0], cb[arg * 4 + 1],
                               cb[arg * 4 + 2], cb[arg * 4 + 3]);
        return;
    }

    __shared__ float smin[256], smax[256];
    const float* src; float* dst; int n;
    switch (blockIdx.x) {
        case 0: src = w0; dst = g_w0q;   n = 320;  break;
        case 1: src = w1; dst = g_wq[0]; n = 4096; break;
        case 2: src = w2; dst = g_wq[1]; n = 4096; break;
        case 3: src = w3; dst = g_wq[2]; n = 4096; break;
        case 4: src = w4; dst = g_w4q;   n = 64;   break;
        case 5: src = b0; dst = g_b0q;   n = 64;   break;
        case 6: src = b1; dst = g_bq[0]; n = 64;   break;
        case 7: src = b2; dst = g_bq[1]; n = 64;   break;
        case 8: src = b3; dst = g_bq[2]; n = 64;   break;
        default: src = b4; dst = g_b4q;  n = 1;    break;
    }
    float mn = INFINITY, mx = -INFINITY;
    for (int i = t; i < n; i += 256) {
        float v = src[i];
        mn = fminf(mn, v); mx = fmaxf(mx, v);
    }
    smin[t] = mn; smax[t] = mx;
    __syncthreads();
    for (int s = 128; s > 0; s >>= 1) {
        if (t < s) {
            smin[t] = fminf(smin[t], smin[t + s]);
            smax[t] = fmaxf(smax[t], smax[t + s]);
        }
        __syncthreads();
    }
    mn = smin[0]; mx = smax[0];
    float scale = fmaxf(mx - mn, 1e-8f) / 63.0f;
    for (int i = t; i < n; i += 256)
        dst[i] = rintf((src[i] - mn) / scale) * scale + mn;   // quantized fp32
}

// ---------------- main tensor-core kernel -----------------------------------
// Direct tf32 weights: B fragments hold tf32_rna(0.5*w_q) (half absorbs the
// doubled-gelu factor). Epilogue: a = d + bias (one add2 per pair). Layer 0 on
// the MMA with natural k8 layout; D->A renaming via sigma(p)=2p|2(p-4)+1.
//
// smem (bytes):
//   0     : wf  — B frags [3l][8kt][8nt][32 lanes] x uint2 = 49152
//   49152 : wf0 — layer0 B frags [8nt][32 lanes] x uint2 = 2048
//   51200 : b0s[64f], 51456: bz[3][64f], 52224: w4s[64f],
//   52480 : b4f[4f], 52496: in5s[5][128f]
#define OFF_WF    0
#define OFF_W0F   49152
#define OFF_B0S   51200
#define OFF_BZ    51456
#define OFF_W4S   52224
#define OFF_B4F   52480
#define OFF_IN5   52496
#define SMEM_BYTES 55056

__global__ void __launch_bounds__(128, 4)
mlp_tc_kernel(const float* __restrict__ x, float* __restrict__ out, int ntiles)
{
    extern __shared__ char smp[];
    const uint2* wf  = (const uint2*)(smp + OFF_WF);
    const uint2* wf0 = (const uint2*)(smp + OFF_W0F);
    float* b0s = (float*)(smp + OFF_B0S);
    float* bz  = (float*)(smp + OFF_BZ);
    float* w4s = (float*)(smp + OFF_W4S);
    float* b4f = (float*)(smp + OFF_B4F);
    float* in5s = (float*)(smp + OFF_IN5);

    int t = threadIdx.x;
    int wid = t >> 5;
    int lane = t & 31;
    int g = lane >> 2;      // row group 0..7
    int tig = lane & 3;     // thread-in-group

    // ---- one-time staging ----
    {
        uint2* wfw = (uint2*)(smp + OFF_WF);
        for (int e = t; e < 6144; e += 128) {
            int el = e & 31, nt = (e >> 5) & 7, kt = (e >> 8) & 7, l = e >> 11;
            int eg = el >> 2, etig = el & 3;
            int j = 8 * nt + eg;
            int k0 = 8 * kt + 2 * etig;
            const float* wl = g_wq[l];
            // halved weights absorb doubled gelu; tf32-rounded once here
            wfw[e] = make_uint2(tf32_rna(0.5f * wl[k0 * 64 + j]),
                                tf32_rna(0.5f * wl[(k0 + 1) * 64 + j]));
        }
        // layer0 B frags (natural m16n8k8 layout; inputs not gelu'd -> no half)
        uint2* wf0w = (uint2*)(smp + OFF_W0F);
        for (int e = t; e < 256; e += 128) {
            int el = e & 31, nt = e >> 5;
            int eg = el >> 2, etig = el & 3;
            int j = 8 * nt + eg;
            uint32_t b0v = tf32_rna(g_w0q[etig * 64 + j]);
            uint32_t b1v = (etig == 0) ? tf32_rna(g_w0q[4 * 64 + j]) : 0u;
            wf0w[e] = make_uint2(b0v, b1v);
        }
    }
    if (t < 64) {
        b0s[t] = g_b0q[t];
        bz[t] = g_bq[0][t]; bz[64 + t] = g_bq[1][t]; bz[128 + t] = g_bq[2][t];
        w4s[t] = 0.5f * g_w4q[t];               // halved: inputs are 2*gelu
        if (t == 0) b4f[0] = g_b4q[0];
    }

    for (int tile = blockIdx.x; tile < ntiles; tile += gridDim.x) {
        __syncthreads();

        // ---- interp: one point per thread -> in5s[5][128] ----
        int gidx = tile * 128 + t;
        {
            float2 xv = __ldg((const float2*)x + gidx);
            float feat = xv.x;
            float tc = (xv.y + 1.0f) * 0.5f;
            float4 gg = make_float4(0.f, 0.f, 0.f, 0.f);
            auto interp_add = [&](const float4* __restrict__ tab, int res) {
                float c = tc * (float)(res - 1);
                int left  = min((int)floorf(c), res - 2);
                int right = max((int)ceilf(c), 1);
                float w = c - (float)left;
                float4 gl = __ldg(tab + left);
                float4 gr = __ldg(tab + right);
                gg.x += (1.0f - w) * gl.x + w * gr.x;
                gg.y += (1.0f - w) * gl.y + w * gr.y;
                gg.z += (1.0f - w) * gl.z + w * gr.z;
                gg.w += (1.0f - w) * gl.w + w * gr.w;
            };
            interp_add(g_grid0, 128);
            interp_add(g_grid1, 512);
            interp_add(g_grid2, 2048);
            in5s[0 * 128 + t] = gg.x;
            in5s[1 * 128 + t] = gg.y;
            in5s[2 * 128 + t] = gg.z;
            in5s[3 * 128 + t] = gg.w;
            in5s[4 * 128 + t] = feat;
        }
        __syncthreads();

        // ---- each warp: 2 sequential m16 sub-tiles ----
        #pragma unroll 1
        for (int s = 0; s < 2; s++) {
            int mt = wid + 4 * s;
            int poff = mt * 16;

            float d[8][4];
            uint32_t A[8][4];            // tf32 A fragments (one per kt)

            // ---- layer 0 (5 -> 64) via MMA (natural k8 layout) ----
            {
                uint32_t A0[4];
                A0[0] = tf32_rna(in5s[tig * 128 + poff + g]);
                A0[1] = tf32_rna(in5s[tig * 128 + poff + g + 8]);
                if (tig == 0) {
                    A0[2] = tf32_rna(in5s[4 * 128 + poff + g]);
                    A0[3] = tf32_rna(in5s[4 * 128 + poff + g + 8]);
                } else {
                    A0[2] = 0u; A0[3] = 0u;
                }
                #pragma unroll
                for (int nt = 0; nt < 8; nt++) {
                    d[nt][0] = 0.f; d[nt][1] = 0.f;
                    d[nt][2] = 0.f; d[nt][3] = 0.f;
                }
                #pragma unroll
                for (int nt = 0; nt < 8; nt++) {
                    uint2 B = wf0[nt * 32 + lane];
                    mma_tf32(d[nt], A0, B.x, B.y);
                }
            }

            // ---- epilogue: d + bias -> 2*gelu -> tf32 A fragments ----
            auto epi = [&](const float* bias) {
                #pragma unroll
                for (int nt = 0; nt < 8; nt++) {
                    int f0 = 8 * nt + 2 * tig;
                    u64 bb2 = *(const u64*)(bias + f0);
                    u64 a01 = add2(pack2(d[nt][0], d[nt][1]), bb2);
                    u64 a23 = add2(pack2(d[nt][2], d[nt][3]), bb2);
                    u64 p01 = gelu2x(a01);
                    u64 p23 = gelu2x(a23);
                    float g0, g1, g2, g3;
                    unpack2(p01, g0, g1);
                    unpack2(p23, g2, g3);
                    // D->A renaming: a0=d0(row g,col 2tig), a1=d2(row g+8),
                    //                a2=d1(col 2tig+1),      a3=d3
                    A[nt][0] = tf32_rna(g0);
                    A[nt][1] = tf32_rna(g2);
                    A[nt][2] = tf32_rna(g1);
                    A[nt][3] = tf32_rna(g3);
                }
            };
            epi(b0s);

            // ---- 3 mma layers (single tf32 product, direct weights) ----
            #pragma unroll 1
            for (int l = 0; l < 3; l++) {
                #pragma unroll
                for (int nt = 0; nt < 8; nt++) {
                    d[nt][0] = 0.f; d[nt][1] = 0.f;
                    d[nt][2] = 0.f; d[nt][3] = 0.f;
                }
                const uint2* wfl = wf + (size_t)l * 8 * 8 * 32;
                #pragma unroll
                for (int kt = 0; kt < 8; kt++) {
                    #pragma unroll
                    for (int nt = 0; nt < 8; nt++) {
                        uint2 B = wfl[(kt * 8 + nt) * 32 + lane];
                        mma_tf32(d[nt], A[kt], B.x, B.y);
                    }
                }
                if (l < 2) epi(bz + 64 * l);
            }

            // ---- final: d + bias b3, 2*gelu, dot w4/2, reduce, tanh ----
            {
                const float* b3 = bz + 128;
                u64 dg = pack2(0.f, 0.f), dg8 = pack2(0.f, 0.f);
                #pragma unroll
                for (int nt = 0; nt < 8; nt++) {
                    int f0 = 8 * nt + 2 * tig;
                    u64 bb2 = *(const u64*)(b3 + f0);
                    u64 a01 = add2(pack2(d[nt][0], d[nt][1]), bb2);
                    u64 a23 = add2(pack2(d[nt][2], d[nt][3]), bb2);
                    u64 w4p = *(const u64*)(w4s + f0);
                    dg  = fma2(gelu2x(a01), w4p, dg);
                    dg8 = fma2(gelu2x(a23), w4p, dg8);
                }
                float a, b, sg, sg8;
                unpack2(dg, a, b);  sg  = a + b;
                unpack2(dg8, a, b); sg8 = a + b;
                sg  += __shfl_xor_sync(0xffffffffu, sg, 1);
                sg  += __shfl_xor_sync(0xffffffffu, sg, 2);
                sg8 += __shfl_xor_sync(0xffffffffu, sg8, 1);
                sg8 += __shfl_xor_sync(0xffffffffu, sg8, 2);
                if (tig == 0) {
                    float bb4 = b4f[0];
                    int base = tile * 128 + poff;
                    out[base + g]     = tanhf(sg + bb4);
                    out[base + g + 8] = tanhf(sg8 + bb4);
                }
            }
        }
    }
}

// ---------------- launch ----------------
extern "C" void kernel_launch(void* const* d_in, const int* in_sizes, int n_in,
                              void* d_out, int out_size)
{
    const float* x    = (const float*)d_in[0];
    const float* cb0  = (const float*)d_in[1];
    const float* ind0 = (const float*)d_in[2];
    const float* cb1  = (const float*)d_in[3];
    const float* ind1 = (const float*)d_in[4];
    const float* cb2  = (const float*)d_in[5];
    const float* ind2 = (const float*)d_in[6];
    const float* w0   = (const float*)d_in[7];
    const float* b0   = (const float*)d_in[8];
    const float* w1   = (const float*)d_in[9];
    const float* b1   = (const float*)d_in[10];
    const float* w2   = (const float*)d_in[11];
    const float* b2   = (const float*)d_in[12];
    const float* w3   = (const float*)d_in[13];
    const float* b3   = (const float*)d_in[14];
    const float* w4   = (const float*)d_in[15];
    const float* b4   = (const float*)d_in[16];

    int N = in_sizes[0] / 2;
    int ntiles = N / 128;

    static int configured = 0;
    if (!configured) {
        cudaFuncSetAttribute(mlp_tc_kernel,
                             cudaFuncAttributeMaxDynamicSharedMemorySize,
                             SMEM_BYTES);
        configured = 1;
    }

    prep_kernel<<<21, 256>>>(w0, w1, w2, w3, w4, b0, b1, b2, b3, b4,
                             ind0, cb0, ind1, cb1, ind2, cb2);
    mlp_tc_kernel<<<1184, 128, SMEM_BYTES>>>(x, (float*)d_out, ntiles);
}

// round 17
// speedup vs baseline: 1.3355x; 1.0531x over previous
#include <cuda_runtime.h>
#include <math.h>
#include <stdint.h>

typedef unsigned long long u64;

// ---------------- device-global scratch (no allocs allowed) ----------------
__device__ __align__(16) float  g_w0q[320];      // 5x64 quantized fp32
__device__ __align__(16) float  g_wq[3][4096];   // w1..w3 quantized fp32 ([k][j])
__device__ __align__(16) float  g_w4q[64];
__device__ __align__(16) float  g_b0q[64];
__device__ __align__(16) float  g_bq[3][64];
__device__ __align__(16) float  g_b4q[4];
__device__ float4 g_grid0[128];
__device__ float4 g_grid1[512];
__device__ float4 g_grid2[2048];

// ---------------- packed helpers -------------------------------------------
__device__ __forceinline__ u64 pack2(float lo, float hi) {
    u64 r;
    asm("mov.b64 %0, {%1, %2};" : "=l"(r) : "f"(lo), "f"(hi));
    return r;
}
__device__ __forceinline__ void unpack2(u64 v, float& lo, float& hi) {
    asm("mov.b64 {%0, %1}, %2;" : "=f"(lo), "=f"(hi) : "l"(v));
}
__device__ __forceinline__ u64 fma2(u64 a, u64 b, u64 c) {
    u64 d;
    asm("fma.rn.f32x2 %0, %1, %2, %3;" : "=l"(d) : "l"(a), "l"(b), "l"(c));
    return d;
}
__device__ __forceinline__ u64 mul2(u64 a, u64 b) {
    u64 d;
    asm("mul.rn.f32x2 %0, %1, %2;" : "=l"(d) : "l"(a), "l"(b));
    return d;
}
__device__ __forceinline__ u64 add2(u64 a, u64 b) {
    u64 d;
    asm("add.rn.f32x2 %0, %1, %2;" : "=l"(d) : "l"(a), "l"(b));
    return d;
}
__device__ __forceinline__ u64 dup2(float c) { return pack2(c, c); }
__device__ __forceinline__ float rcp_fast(float x) {
    float r; asm("rcp.approx.f32 %0, %1;" : "=f"(r) : "f"(x)); return r;
}
__device__ __forceinline__ float ex2_fast(float x) {
    float r; asm("ex2.approx.f32 %0, %1;" : "=f"(r) : "f"(x)); return r;
}
__device__ __forceinline__ u64 rcp2(u64 a) {
    float l, h; unpack2(a, l, h); return pack2(rcp_fast(l), rcp_fast(h));
}
__device__ __forceinline__ u64 ex22(u64 a) {
    float l, h; unpack2(a, l, h); return pack2(ex2_fast(l), ex2_fast(h));
}
__device__ __forceinline__ uint32_t tf32_rna(float x) {
    uint32_t r;
    asm("cvt.rna.tf32.f32 %0, %1;" : "=r"(r) : "f"(x));
    return r;
}

// packed DOUBLED GELU, A&S 7.1.25 3-term (|erf err| <= 2.5e-5):
// returns 2*gelu(x) = x + |x|*erf(|x|/sqrt2); factor 2 compensated by
// halving staged weights (w1..w3, w4) exactly in staging.
__device__ __forceinline__ u64 gelu2x(u64 v) {
    const u64 ABS2 = 0x7fffffff7fffffffULL;
    u64 ONE2 = dup2(1.0f);
    u64 ax = v & ABS2;
    u64 t  = rcp2(fma2(ax, dup2(0.33267982f), ONE2));
    u64 q  = fma2(dup2(-0.7478556f), t, dup2(0.0958798f));
    q = fma2(q, t, dup2(-0.3480242f));
    u64 s  = mul2(q, t);
    u64 x2 = mul2(ax, ax);
    u64 e  = ex22(mul2(x2, dup2(-0.7213475204f)));
    u64 ea = fma2(s, e, ONE2);              // erf(|x|/sqrt2)
    return fma2(ax, ea, v);                 // x + |x|*erf = 2*gelu(x)
}

// tf32 tensor-core mma (base PTX, sm_80+): D += A x B  (m16n8k8)
// A operands carry raw f32 bits: HW truncates to tf32 (rel err <= 2^-11,
// empirically anchored at ~1.7e-4 output in R11 — inside budget).
__device__ __forceinline__ void mma_tf32(float d[4], const uint32_t a[4],
                                         uint32_t b0, uint32_t b1) {
    asm volatile(
        "mma.sync.aligned.m16n8k8.row.col.f32.tf32.tf32.f32 "
        "{%0,%1,%2,%3}, {%4,%5,%6,%7}, {%8,%9}, {%0,%1,%2,%3};"
        : "+f"(d[0]), "+f"(d[1]), "+f"(d[2]), "+f"(d[3])
        : "r"(a[0]), "r"(a[1]), "r"(a[2]), "r"(a[3]), "r"(b0), "r"(b1));
}

// ---------------- merged prep: quantization + grid tables -------------------
__global__ void prep_kernel(const float* w0, const float* w1, const float* w2,
                            const float* w3, const float* w4,
                            const float* b0, const float* b1, const float* b2,
                            const float* b3, const float* b4,
                            const float* ind0, const float* cb0,
                            const float* ind1, const float* cb1,
                            const float* ind2, const float* cb2)
{
    int t = threadIdx.x;
    if (blockIdx.x >= 10) {
        int idx = (blockIdx.x - 10) * 256 + t;
        const float* ind; const float* cb; float4* dst; int row;
        if (idx < 128)       { ind = ind0; cb = cb0; dst = g_grid0; row = idx; }
        else if (idx < 640)  { ind = ind1; cb = cb1; dst = g_grid1; row = idx - 128; }
        else if (idx < 2688) { ind = ind2; cb = cb2; dst = g_grid2; row = idx - 640; }
        else return;
        const float* r = ind + (long)row * 64;
        float best = r[0]; int arg = 0;
        #pragma unroll
        for (int j = 1; j < 64; j++) {
            float v = r[j];
            if (v > best) { best = v; arg = j; }   // strict > == first-occurrence
        }
        dst[row] = make_float4(cb[arg * 4 + 0], cb[arg * 4 + 1],
                               cb[arg * 4 + 2], cb[arg * 4 + 3]);
        return;
    }

    __shared__ float smin[256], smax[256];
    const float* src; float* dst; int n;
    switch (blockIdx.x) {
        case 0: src = w0; dst = g_w0q;   n = 320;  break;
        case 1: src = w1; dst = g_wq[0]; n = 4096; break;
        case 2: src = w2; dst = g_wq[1]; n = 4096; break;
        case 3: src = w3; dst = g_wq[2]; n = 4096; break;
        case 4: src = w4; dst = g_w4q;   n = 64;   break;
        case 5: src = b0; dst = g_b0q;   n = 64;   break;
        case 6: src = b1; dst = g_bq[0]; n = 64;   break;
        case 7: src = b2; dst = g_bq[1]; n = 64;   break;
        case 8: src = b3; dst = g_bq[2]; n = 64;   break;
        default: src = b4; dst = g_b4q;  n = 1;    break;
    }
    float mn = INFINITY, mx = -INFINITY;
    for (int i = t; i < n; i += 256) {
        float v = src[i];
        mn = fminf(mn, v); mx = fmaxf(mx, v);
    }
    smin[t] = mn; smax[t] = mx;
    __syncthreads();
    for (int s = 128; s > 0; s >>= 1) {
        if (t < s) {
            smin[t] = fminf(smin[t], smin[t + s]);
            smax[t] = fmaxf(smax[t], smax[t + s]);
        }
        __syncthreads();
    }
    mn = smin[0]; mx = smax[0];
    float scale = fmaxf(mx - mn, 1e-8f) / 63.0f;
    for (int i = t; i < n; i += 256)
        dst[i] = rintf((src[i] - mn) / scale) * scale + mn;   // quantized fp32
}

// ---------------- main tensor-core kernel -----------------------------------
// Direct tf32 weights: B fragments hold tf32_rna(0.5*w_q) (half absorbs the
// doubled-gelu factor). A fragments carry raw f32 bits (HW tf32 truncation;
// no cvt on the hot path). Layer 0 on the MMA (natural k8 layout); D->A is a
// register renaming via sigma(p)=2p|2(p-4)+1.
//
// smem (bytes):
//   0     : wf  — B frags [3l][8kt][8nt][32 lanes] x uint2 = 49152
//   49152 : wf0 — layer0 B frags [8nt][32 lanes] x uint2 = 2048
//   51200 : b0s[64f], 51456: bz[3][64f], 52224: w4s[64f],
//   52480 : b4f[4f], 52496: in5s[5][128f]
#define OFF_WF    0
#define OFF_W0F   49152
#define OFF_B0S   51200
#define OFF_BZ    51456
#define OFF_W4S   52224
#define OFF_B4F   52480
#define OFF_IN5   52496
#define SMEM_BYTES 55056

__global__ void __launch_bounds__(128, 4)
mlp_tc_kernel(const float* __restrict__ x, float* __restrict__ out, int ntiles)
{
    extern __shared__ char smp[];
    const uint2* wf  = (const uint2*)(smp + OFF_WF);
    const uint2* wf0 = (const uint2*)(smp + OFF_W0F);
    float* b0s = (float*)(smp + OFF_B0S);
    float* bz  = (float*)(smp + OFF_BZ);
    float* w4s = (float*)(smp + OFF_W4S);
    float* b4f = (float*)(smp + OFF_B4F);
    float* in5s = (float*)(smp + OFF_IN5);

    int t = threadIdx.x;
    int wid = t >> 5;
    int lane = t & 31;
    int g = lane >> 2;      // row group 0..7
    int tig = lane & 3;     // thread-in-group

    // ---- one-time staging ----
    {
        uint2* wfw = (uint2*)(smp + OFF_WF);
        for (int e = t; e < 6144; e += 128) {
            int el = e & 31, nt = (e >> 5) & 7, kt = (e >> 8) & 7, l = e >> 11;
            int eg = el >> 2, etig = el & 3;
            int j = 8 * nt + eg;
            int k0 = 8 * kt + 2 * etig;
            const float* wl = g_wq[l];
            // halved weights absorb doubled gelu; tf32-rounded once here
            wfw[e] = make_uint2(tf32_rna(0.5f * wl[k0 * 64 + j]),
                                tf32_rna(0.5f * wl[(k0 + 1) * 64 + j]));
        }
        // layer0 B frags (natural m16n8k8 layout; inputs not gelu'd -> no half)
        uint2* wf0w = (uint2*)(smp + OFF_W0F);
        for (int e = t; e < 256; e += 128) {
            int el = e & 31, nt = e >> 5;
            int eg = el >> 2, etig = el & 3;
            int j = 8 * nt + eg;
            uint32_t b0v = tf32_rna(g_w0q[etig * 64 + j]);
            uint32_t b1v = (etig == 0) ? tf32_rna(g_w0q[4 * 64 + j]) : 0u;
            wf0w[e] = make_uint2(b0v, b1v);
        }
    }
    if (t < 64) {
        b0s[t] = g_b0q[t];
        bz[t] = g_bq[0][t]; bz[64 + t] = g_bq[1][t]; bz[128 + t] = g_bq[2][t];
        w4s[t] = 0.5f * g_w4q[t];               // halved: inputs are 2*gelu
        if (t == 0) b4f[0] = g_b4q[0];
    }

    for (int tile = blockIdx.x; tile < ntiles; tile += gridDim.x) {
        __syncthreads();

        // ---- interp: one point per thread -> in5s[5][128] ----
        int gidx = tile * 128 + t;
        {
            float2 xv = __ldg((const float2*)x + gidx);
            float feat = xv.x;
            float tc = (xv.y + 1.0f) * 0.5f;
            float4 gg = make_float4(0.f, 0.f, 0.f, 0.f);
            auto interp_add = [&](const float4* __restrict__ tab, int res) {
                float c = tc * (float)(res - 1);
                int left  = min((int)floorf(c), res - 2);
                int right = max((int)ceilf(c), 1);
                float w = c - (float)left;
                float4 gl = __ldg(tab + left);
                float4 gr = __ldg(tab + right);
                gg.x += (1.0f - w) * gl.x + w * gr.x;
                gg.y += (1.0f - w) * gl.y + w * gr.y;
                gg.z += (1.0f - w) * gl.z + w * gr.z;
                gg.w += (1.0f - w) * gl.w + w * gr.w;
            };
            interp_add(g_grid0, 128);
            interp_add(g_grid1, 512);
            interp_add(g_grid2, 2048);
            in5s[0 * 128 + t] = gg.x;
            in5s[1 * 128 + t] = gg.y;
            in5s[2 * 128 + t] = gg.z;
            in5s[3 * 128 + t] = gg.w;
            in5s[4 * 128 + t] = feat;
        }
        __syncthreads();

        // ---- each warp: 2 sequential m16 sub-tiles ----
        #pragma unroll 1
        for (int s = 0; s < 2; s++) {
            int mt = wid + 4 * s;
            int poff = mt * 16;

            float d[8][4];
            uint32_t A[8][4];            // A fragments, raw f32 bits

            // ---- layer 0 (5 -> 64) via MMA (natural k8 layout) ----
            {
                uint32_t A0[4];
                A0[0] = __float_as_uint(in5s[tig * 128 + poff + g]);
                A0[1] = __float_as_uint(in5s[tig * 128 + poff + g + 8]);
                if (tig == 0) {
                    A0[2] = __float_as_uint(in5s[4 * 128 + poff + g]);
                    A0[3] = __float_as_uint(in5s[4 * 128 + poff + g + 8]);
                } else {
                    A0[2] = 0u; A0[3] = 0u;
                }
                #pragma unroll
                for (int nt = 0; nt < 8; nt++) {
                    d[nt][0] = 0.f; d[nt][1] = 0.f;
                    d[nt][2] = 0.f; d[nt][3] = 0.f;
                }
                #pragma unroll
                for (int nt = 0; nt < 8; nt++) {
                    uint2 B = wf0[nt * 32 + lane];
                    mma_tf32(d[nt], A0, B.x, B.y);
                }
            }

            // ---- epilogue: d + bias -> 2*gelu -> raw-bit A fragments ----
            auto epi = [&](const float* bias) {
                #pragma unroll
                for (int nt = 0; nt < 8; nt++) {
                    int f0 = 8 * nt + 2 * tig;
                    u64 bb2 = *(const u64*)(bias + f0);
                    u64 a01 = add2(pack2(d[nt][0], d[nt][1]), bb2);
                    u64 a23 = add2(pack2(d[nt][2], d[nt][3]), bb2);
                    u64 p01 = gelu2x(a01);
                    u64 p23 = gelu2x(a23);
                    float g0, g1, g2, g3;
                    unpack2(p01, g0, g1);
                    unpack2(p23, g2, g3);
                    // D->A renaming: a0=d0(row g,col 2tig), a1=d2(row g+8),
                    //                a2=d1(col 2tig+1),      a3=d3
                    A[nt][0] = __float_as_uint(g0);
                    A[nt][1] = __float_as_uint(g2);
                    A[nt][2] = __float_as_uint(g1);
                    A[nt][3] = __float_as_uint(g3);
                }
            };
            epi(b0s);

            // ---- 3 mma layers (single tf32 product, direct weights) ----
            #pragma unroll 1
            for (int l = 0; l < 3; l++) {
                #pragma unroll
                for (int nt = 0; nt < 8; nt++) {
                    d[nt][0] = 0.f; d[nt][1] = 0.f;
                    d[nt][2] = 0.f; d[nt][3] = 0.f;
                }
                const uint2* wfl = wf + (size_t)l * 8 * 8 * 32;
                #pragma unroll
                for (int kt = 0; kt < 8; kt++) {
                    #pragma unroll
                    for (int nt = 0; nt < 8; nt++) {
                        uint2 B = wfl[(kt * 8 + nt) * 32 + lane];
                        mma_tf32(d[nt], A[kt], B.x, B.y);
                    }
                }
                if (l < 2) epi(bz + 64 * l);
            }

            // ---- final: d + bias b3, 2*gelu, dot w4/2, reduce, tanh ----
            {
                const float* b3 = bz + 128;
                u64 dg = pack2(0.f, 0.f), dg8 = pack2(0.f, 0.f);
                #pragma unroll
                for (int nt = 0; nt < 8; nt++) {
                    int f0 = 8 * nt + 2 * tig;
                    u64 bb2 = *(const u64*)(b3 + f0);
                    u64 a01 = add2(pack2(d[nt][0], d[nt][1]), bb2);
                    u64 a23 = add2(pack2(d[nt][2], d[nt][3]), bb2);
                    u64 w4p = *(const u64*)(w4s + f0);
                    dg  = fma2(gelu2x(a01), w4p, dg);
                    dg8 = fma2(gelu2x(a23), w4p, dg8);
                }
                float a, b, sg, sg8;
                unpack2(dg, a, b);  sg  = a + b;
                unpack2(dg8, a, b); sg8 = a + b;
                sg  += __shfl_xor_sync(0xffffffffu, sg, 1);
                sg  += __shfl_xor_sync(0xffffffffu, sg, 2);
                sg8 += __shfl_xor_sync(0xffffffffu, sg8, 1);
                sg8 += __shfl_xor_sync(0xffffffffu, sg8, 2);
                if (tig == 0) {
                    float bb4 = b4f[0];
                    int base = tile * 128 + poff;
                    out[base + g]     = tanhf(sg + bb4);
                    out[base + g + 8] = tanhf(sg8 + bb4);
                }
            }
        }
    }
}

// ---------------- launch ----------------
extern "C" void kernel_launch(void* const* d_in, const int* in_sizes, int n_in,
                              void* d_out, int out_size)
{
    const float* x    = (const float*)d_in[0];
    const float* cb0  = (const float*)d_in[1];
    const float* ind0 = (const float*)d_in[2];
    const float* cb1  = (const float*)d_in[3];
    const float* ind1 = (const float*)d_in[4];
    const float* cb2  = (const float*)d_in[5];
    const float* ind2 = (const float*)d_in[6];
    const float* w0   = (const float*)d_in[7];
    const float* b0   = (const float*)d_in[8];
    const float* w1   = (const float*)d_in[9];
    const float* b1   = (const float*)d_in[10];
    const float* w2   = (const float*)d_in[11];
    const float* b2   = (const float*)d_in[12];
    const float* w3   = (const float*)d_in[13];
    const float* b3   = (const float*)d_in[14];
    const float* w4   = (const float*)d_in[15];
    const float* b4   = (const float*)d_in[16];

    int N = in_sizes[0] / 2;
    int ntiles = N / 128;

    static int configured = 0;
    if (!configured) {
        cudaFuncSetAttribute(mlp_tc_kernel,
                             cudaFuncAttributeMaxDynamicSharedMemorySize,
                             SMEM_BYTES);
        configured = 1;
    }

    prep_kernel<<<21, 256>>>(w0, w1, w2, w3, w4, b0, b1, b2, b3, b4,
                             ind0, cb0, ind1, cb1, ind2, cb2);
    mlp_tc_kernel<<<1184, 128, SMEM_BYTES>>>(x, (float*)d_out, ntiles);
}